// round 17
// baseline (speedup 1.0000x reference)
#include <cuda_runtime.h>
#include <cstdint>

// KANStressPredictor: elementwise over [B,T,3] f32 strain.
//   c00=2s0+1, c11=2s1+1, c01=s2
//   det=c00*c11-c01^2, l=log2(det)
//   mean=0.5*(c00+c11), rad=sqrt(0.25*(c00-c11)^2 + c01^2)
//   out_k = exp2(ki0*(0.5*log2(mean -/+ rad) - l/6)),  out_2 = 0.5*ln2*l*ki1
//
// R13: persistent grid-stride launch. Previous launches ran ~7 waves of CTAs
// (grid=8192, occ=8/SM); each wave pays ramp/drain where HBM sits idle plus
// T_wave_trans (~2360cyc) per transition. One resident wave (152 SMs x 8
// blocks) loops over the data instead: no wave transitions, and the loop
// lets ptxas pipeline next-iteration LDG.128s under current compute/stores.

#define THREADS      256
#define BLOCKS_PER_SM 8
#define NUM_SMS      152           // GB300

__device__ __forceinline__ void kan_point(float s0, float s1, float s2,
                                          float ki0, float ki1,
                                          float& o0, float& o1, float& o2) {
    const float c00 = fmaf(2.0f, s0, 1.0f);
    const float c11 = fmaf(2.0f, s1, 1.0f);
    const float c01 = s2;

    const float det = fmaf(c00, c11, -c01 * c01);
    const float l   = __log2f(det);                 // log2(det)

    const float mean = 0.5f * (c00 + c11);
    const float hd   = 0.5f * (c00 - c11);
    const float rad  = sqrtf(fmaf(hd, hd, c01 * c01));

    const float lm = __log2f(mean - rad);           // log2(lambda0)
    const float lp = __log2f(mean + rad);           // log2(lambda1)

    const float half_ki0 = 0.5f * ki0;
    const float base = ki0 * (l * (-1.0f / 6.0f));  // ki0*log2(det^(-1/6))

    o0 = exp2f(fmaf(half_ki0, lm, base));           // independent MUFU chains
    o1 = exp2f(fmaf(half_ki0, lp, base));
    o2 = (0.5f * 0.69314718055994531f) * l * ki1;   // log(sqrt(det)) * ki1
}

__global__ __launch_bounds__(THREADS, BLOCKS_PER_SM)
void kan_persist_kernel(const float4* __restrict__ in, float4* __restrict__ out,
                        const float* __restrict__ ki0p, const float* __restrict__ ki1p,
                        int n_groups) {
    const int tid    = blockIdx.x * THREADS + threadIdx.x;
    const int stride = gridDim.x * THREADS;

    const float ki0 = __ldg(ki0p);
    const float ki1 = __ldg(ki1p);

    for (int g = tid; g < n_groups; g += stride) {
        // 3 contiguous float4 = 4 points, front-batched loads; across loop
        // iterations ptxas overlaps the next trio with this compute.
        const float4 a = in[3 * g + 0];
        const float4 b = in[3 * g + 1];
        const float4 c = in[3 * g + 2];

        float o[12];
        kan_point(a.x, a.y, a.z, ki0, ki1, o[0], o[1],  o[2]);
        kan_point(a.w, b.x, b.y, ki0, ki1, o[3], o[4],  o[5]);
        kan_point(b.z, b.w, c.x, ki0, ki1, o[6], o[7],  o[8]);
        kan_point(c.y, c.z, c.w, ki0, ki1, o[9], o[10], o[11]);

        out[3 * g + 0] = make_float4(o[0], o[1], o[2],  o[3]);
        out[3 * g + 1] = make_float4(o[4], o[5], o[6],  o[7]);
        out[3 * g + 2] = make_float4(o[8], o[9], o[10], o[11]);
    }
}

// Scalar tail (points not divisible by 4). Normally 0 launches.
__global__ void kan_tail_kernel(const float* __restrict__ in, float* __restrict__ out,
                                const float* __restrict__ ki0p, const float* __restrict__ ki1p,
                                int start_point, int n_points) {
    const int p = start_point + blockIdx.x * blockDim.x + threadIdx.x;
    if (p >= n_points) return;
    const float ki0 = __ldg(ki0p);
    const float ki1 = __ldg(ki1p);
    float o0, o1, o2;
    kan_point(in[3 * p + 0], in[3 * p + 1], in[3 * p + 2], ki0, ki1, o0, o1, o2);
    out[3 * p + 0] = o0;
    out[3 * p + 1] = o1;
    out[3 * p + 2] = o2;
}

extern "C" void kernel_launch(void* const* d_in, const int* in_sizes, int n_in,
                              void* d_out, int out_size) {
    const float* strain = (const float*)d_in[0];
    const float* ki0p   = (const float*)d_in[1];
    const float* ki1p   = (const float*)d_in[2];
    float* out          = (float*)d_out;

    const int n_floats = in_sizes[0];          // B*T*3
    const int n_points = n_floats / 3;
    const int n_groups = n_points / 4;         // 4 points per loop step
    const int tail     = n_points - n_groups * 4;

    if (n_groups > 0) {
        int blocks = NUM_SMS * BLOCKS_PER_SM;  // one resident wave
        const int max_blocks = (n_groups + THREADS - 1) / THREADS;
        if (blocks > max_blocks) blocks = max_blocks;
        kan_persist_kernel<<<blocks, THREADS>>>(
            (const float4*)strain, (float4*)out, ki0p, ki1p, n_groups);
    }
    if (tail > 0) {
        kan_tail_kernel<<<1, 256>>>(strain, out, ki0p, ki1p, n_groups * 4, n_points);
    }
}